// round 16
// baseline (speedup 1.0000x reference)
#include <cuda_runtime.h>

// ---------------------------------------------------------------------------
// WaveletConv in 3 launches:
//   fwd123 : fwd levels 1-3 fused (halo recompute), x -> lo3 + hi1..hi3
//            grouped-by-2 outputs: 3 LDS.128 window, shared filter regs,
//            paired STS.64/STG.64 stores, hoisted hi-window predicates
//   mid    : fwd 4-8 + inv 7-2 fused per-channel in smem (lo3 -> prev2)
//   inv10  : inv levels 1-0 fused, prev2 + hi2 + hi1 -> out (frozen optimum)
// Packed f32x2 FMA; conflict-free LDS.128 windows; CTA-uniform packed
// filters in shared memory, fetched as ulonglong2 pairs (broadcast LDS.128).
// ---------------------------------------------------------------------------

#define NCH      128
#define TLEN     131072
#define FNT      512    // mid kernel threads

// hi offsets padded to multiples of 4 floats (16B)
__device__ __constant__ int c_HOFF[8] = {0, 65540, 98312, 114700, 122896, 126996, 129048, 130076};
#define HI_STRIDE 130592

__device__ __constant__ float c_WLO[10] = {0.003335725285001549f, -0.012580751999015526f,
    -0.006241490213011705f, 0.07757149384006515f, -0.03224486958502952f,
    -0.24229488706619015f, 0.13842814590110342f, 0.7243085284385744f,
    0.6038292697974729f, 0.160102397974125f};
__device__ __constant__ float c_WHI[10] = {-0.160102397974125f, 0.6038292697974729f,
    -0.7243085284385744f, 0.13842814590110342f, 0.24229488706619015f,
    -0.03224486958502952f, -0.07757149384006515f, -0.006241490213011705f,
    0.012580751999015526f, 0.003335725285001549f};

// Static scratch (allocation-free rule)
__device__ __align__(16) float g_hi[NCH * HI_STRIDE];    // hi1..hi8
__device__ __align__(16) float g_bufA[NCH * 32772];      // prev2
__device__ __align__(16) float g_bufB[NCH * 65540];      // lo3

// ---- packed f32x2 helpers --------------------------------------------------
typedef unsigned long long ull;

__device__ __forceinline__ ull pk2(float lo, float hi) {
    ull r; asm("mov.b64 %0, {%1, %2};" : "=l"(r) : "f"(lo), "f"(hi)); return r;
}
__device__ __forceinline__ ull bcast2(float v) {
    ull r; asm("mov.b64 %0, {%1, %1};" : "=l"(r) : "f"(v)); return r;
}
__device__ __forceinline__ void ffma2(ull& d, ull a, ull b) {
    asm("fma.rn.f32x2 %0, %1, %2, %3;" : "=l"(d) : "l"(a), "l"(b), "l"(d));
}
__device__ __forceinline__ void add2(ull& d, ull a, ull b) {
    asm("add.rn.f32x2 %0, %1, %2;" : "=l"(d) : "l"(a), "l"(b));
}
__device__ __forceinline__ void unpk2(float& lo, float& hi, ull r) {
    asm("mov.b64 {%0, %1}, %2;" : "=f"(lo), "=f"(hi) : "l"(r));
}

// load 20 floats from 16B-aligned smem pointer via 5 conflict-free LDS.128
__device__ __forceinline__ void load20(float* w, const float* p)
{
    const float4* q = reinterpret_cast<const float4*>(p);
    #pragma unroll
    for (int v = 0; v < 5; v++) {
        const float4 t = q[v];
        w[4 * v] = t.x; w[4 * v + 1] = t.y; w[4 * v + 2] = t.z; w[4 * v + 3] = t.w;
    }
}

// 4-t group: acc[k] += P[j] * w[j+k]. P is 16B-aligned CTA-uniform shared;
// fetch filter pairs as one broadcast LDS.128 (halves filter LDS count).
// Per-accumulator add order stays j-ascending -> bit-identical numerics.
__device__ __forceinline__ void inv_acc4(const float* w, const ull* P, ull* acc)
{
    #pragma unroll
    for (int j = 0; j < 16; j += 2) {
        const ulonglong2 pj2 = *reinterpret_cast<const ulonglong2*>(P + j);
        ffma2(acc[0], bcast2(w[j]),     pj2.x);
        ffma2(acc[1], bcast2(w[j + 1]), pj2.x);
        ffma2(acc[2], bcast2(w[j + 2]), pj2.x);
        ffma2(acc[3], bcast2(w[j + 3]), pj2.x);
        ffma2(acc[0], bcast2(w[j + 1]), pj2.y);
        ffma2(acc[1], bcast2(w[j + 2]), pj2.y);
        ffma2(acc[2], bcast2(w[j + 3]), pj2.y);
        ffma2(acc[3], bcast2(w[j + 4]), pj2.y);
    }
}

// full inverse group: 4 consecutive t from smem windows sp/sh (16B-aligned).
__device__ __forceinline__ void inv_group4(const float* sp, const float* sh,
                                           const ull* PL, const ull* PH, ull* acc)
{
    acc[0] = acc[1] = acc[2] = acc[3] = 0ull;
    float w[20];
    load20(w, sp); inv_acc4(w, PL, acc);
    load20(w, sh); inv_acc4(w, PH, acc);
}

// load packed per-(channel,level) filters into CTA shared arrays (tid<16).
// Caller must __syncthreads() before using them.
__device__ __forceinline__ void load_filters_smem(
    const float* __restrict__ filt, int ch, int i, ull* sPL, ull* sPH, int tid)
{
    if (tid < 16) {
        const float2* f2 = reinterpret_cast<const float2*>(filt + ((size_t)ch * 8 + (size_t)i) * 64);
        const float2 a = f2[tid];
        const float2 b = f2[16 + tid];
        sPL[tid] = pk2(a.y, a.x);
        sPH[tid] = pk2(b.y, b.x);
    }
}

// stage `cnt` floats from src[base..base+cnt) into smem buf (buf[q]=src[base+q]).
__device__ __forceinline__ void stage_vec(float* buf, const float* __restrict__ src,
                                          int base, int cnt, int len, bool interior, int tid, int nthr)
{
    if (interior) {
        if (tid < 3) buf[tid] = src[base + tid];
        const int nv = (cnt - 3) >> 2;              // float4 count
        const int rem = cnt - 3 - 4 * nv;           // 0..3 tail scalars
        if (tid >= 3 && tid < 3 + rem) buf[cnt - 1 - (tid - 3)] = src[base + cnt - 1 - (tid - 3)];
        const float4* s4 = reinterpret_cast<const float4*>(src + base + 3);
        for (int v = tid; v < nv; v += nthr) {
            const float4 w = s4[v];
            const int q = 3 + 4 * v;
            buf[q] = w.x; buf[q + 1] = w.y; buf[q + 2] = w.z; buf[q + 3] = w.w;
        }
    } else {
        for (int q = tid; q < cnt; q += nthr) {
            const int g = base + q;
            buf[q] = ((unsigned)g < (unsigned)len) ? src[g] : 0.0f;
        }
    }
}

// ---------------------------------------------------------------------------
// fwd123: levels 1-3. CTA owns lo3[c3, c3+512); recomputes lo1/lo2 in smem.
// Grouped-by-2 forward levels.
// ---------------------------------------------------------------------------
#define FW_D3  512
#define FW_SX  4160   // >= szx = 4152 (+ group over-read slack)
#define FW_SL1 2080   // >= sz1 = 2072
#define FW_SMEM ((FW_SX + FW_SL1) * 4)

// grouped-by-2 forward level into smem lo + global hi.
// SB[q] = in[aN + q] (zero-padded staging done by caller's previous level).
// lo written to SL[q] for all q < szN (0 outside [qneg, qvalid)).
// hi written to hig[q] (hig = hi_global + aN) for q in [qlo, qhi).
__device__ __forceinline__ void fwd_level_g2(
    const float* SB, float* SL, int szN, float* __restrict__ hig,
    int qneg, int qvalid, int qlo, int qhi, int tid, const ull* W2)
{
    const int ngrp = szN >> 1;   // szN always even here
    for (int g = tid; g < ngrp; g += 256) {
        const int q0 = 2 * g;
        float w[12];
        const float4* p4 = reinterpret_cast<const float4*>(SB + 2 * q0);
        #pragma unroll
        for (int v = 0; v < 3; v++) {
            const float4 t = p4[v];
            w[4 * v] = t.x; w[4 * v + 1] = t.y; w[4 * v + 2] = t.z; w[4 * v + 3] = t.w;
        }
        ull a0 = 0ull, a1 = 0ull;
        #pragma unroll
        for (int k = 0; k < 10; k++) {
            const ull pk = W2[k];
            ffma2(a0, bcast2(w[k]),     pk);
            ffma2(a1, bcast2(w[k + 2]), pk);
        }
        float lo0, hv0, lo1, hv1;
        unpk2(lo0, hv0, a0);
        unpk2(lo1, hv1, a1);
        // zero lo outside valid n-range (rare: only boundary groups)
        if (q0 < qneg || q0 >= qvalid)         lo0 = 0.0f;
        if (q0 + 1 < qneg || q0 + 1 >= qvalid) lo1 = 0.0f;
        *reinterpret_cast<float2*>(SL + q0) = make_float2(lo0, lo1);
        // hi store: fast path both-in-window
        if (q0 >= qlo && q0 + 1 < qhi) {
            hig[q0]     = hv0;
            hig[q0 + 1] = hv1;
        } else {
            if (q0 >= qlo && q0 < qhi)         hig[q0]     = hv0;
            if (q0 + 1 >= qlo && q0 + 1 < qhi) hig[q0 + 1] = hv1;
        }
    }
}

__global__ void __launch_bounds__(256)
fwd123(const float* __restrict__ x)
{
    extern __shared__ __align__(16) float s[];
    float* SX  = s;             // x stage; aliased by lo2 later
    float* SL1 = s + FW_SX;
    float* SL2 = s;

    const int ch = blockIdx.y, b = blockIdx.x, tid = threadIdx.x;
    const int L1 = 65537, L2 = 32769, L3 = 16385;

    const int c3 = b * FW_D3;
    const int d3  = min(c3 + FW_D3, L3);
    const int a2  = 2 * c3 - 5, sz2 = 2 * (d3 - c3) + 8;
    const int a1  = 2 * a2 - 5, sz1 = 2 * sz2 + 8;
    const int ax  = 2 * a1 - 5, szx = 2 * sz1 + 8;

    const float* __restrict__ xr = x + (size_t)ch * TLEN;
    const bool xint = (ax >= 0) && (ax + szx <= TLEN);
    stage_vec(SX, xr, ax, szx, TLEN, xint, tid, 256);
    __syncthreads();

    ull W2[10];
    #pragma unroll
    for (int k = 0; k < 10; k++) W2[k] = pk2(c_WLO[k], c_WHI[k]);

    // ---- level 1: SX -> SL1 (lo1), hi1 -> global owned window ----
    {
        float* __restrict__ hi1 = g_hi + (size_t)ch * HI_STRIDE;
        const int qneg   = (a1 < 0) ? -a1 : 0;
        const int qvalid = L1 - a1;                       // may exceed sz1 (fine)
        const int qlo    = 4 * c3 - a1;                   // owned window start
        const int qhi    = min(4 * c3 + 4 * FW_D3, L1) - a1;
        fwd_level_g2(SX, SL1, sz1, hi1 + a1, qneg, qvalid, qlo, qhi, tid, W2);
    }
    __syncthreads();

    // ---- level 2: SL1 -> SL2 (aliases SX), hi2 -> global owned window ----
    {
        float* __restrict__ hi2 = g_hi + (size_t)ch * HI_STRIDE + c_HOFF[1];
        const int qneg   = (a2 < 0) ? -a2 : 0;
        const int qvalid = L2 - a2;
        const int qlo    = 2 * c3 - a2;
        const int qhi    = min(2 * c3 + 2 * FW_D3, L2) - a2;
        fwd_level_g2(SL1, SL2, sz2, hi2 + a2, qneg, qvalid, qlo, qhi, tid, W2);
    }
    __syncthreads();

    // ---- level 3: SL2 -> lo3 + hi3 global (all owned & valid) ----
    {
        float* __restrict__ lo3 = g_bufB + (size_t)ch * 65540 + c3;
        float* __restrict__ hi3 = g_hi + (size_t)ch * HI_STRIDE + c_HOFF[2] + c3;
        const int cnt  = d3 - c3;            // 512, or 1 on the tail block
        const int ngrp = (cnt + 1) >> 1;
        for (int g = tid; g < ngrp; g += 256) {
            const int q0 = 2 * g;
            float w[12];
            const float4* p4 = reinterpret_cast<const float4*>(SL2 + 2 * q0);
            #pragma unroll
            for (int v = 0; v < 3; v++) {
                const float4 t = p4[v];
                w[4 * v] = t.x; w[4 * v + 1] = t.y; w[4 * v + 2] = t.z; w[4 * v + 3] = t.w;
            }
            ull a0 = 0ull, a1 = 0ull;
            #pragma unroll
            for (int k = 0; k < 10; k++) {
                const ull pk = W2[k];
                ffma2(a0, bcast2(w[k]),     pk);
                ffma2(a1, bcast2(w[k + 2]), pk);
            }
            float lo0, hv0, lo1, hv1;
            unpk2(lo0, hv0, a0);
            unpk2(lo1, hv1, a1);
            if (q0 + 1 < cnt) {
                *reinterpret_cast<float2*>(lo3 + q0) = make_float2(lo0, lo1);
                *reinterpret_cast<float2*>(hi3 + q0) = make_float2(hv0, hv1);
            } else {
                lo3[q0] = lo0;
                hi3[q0] = hv0;
            }
        }
    }
}

// ---------------------------------------------------------------------------
// inv10: levels 1+0 fused (frozen optimum). CTA owns 1024 level-0 t values.
// ---------------------------------------------------------------------------
__global__ void __launch_bounds__(256)
inv10(const float* __restrict__ filt, float* __restrict__ outg)
{
    __shared__ __align__(16) float bp2s[544], bh2s[544];
    __shared__ __align__(16) float bh1s[1040];
    __shared__ __align__(16) float bp1s[1048];
    __shared__ __align__(16) ull sPL1[16], sPH1[16], sPL0[16], sPH0[16];

    const int ch = blockIdx.y, b = blockIdx.x, tid = threadIdx.x;
    const int Nout1 = 65537, Nout2 = 32769;

    const int Ta  = 1024 * b;       // level-0 t range [Ta, Ta+1024)
    const int g1  = Ta - 7;         // prev1/hi1 buffer origin
    const int T1a = 512 * b - 4;    // level-1 first t (mult of 4)
    const int g2  = T1a - 7;        // prev2/hi2 buffer origin

    const float* __restrict__ p2g = g_bufA + (size_t)ch * 32772;
    const float* __restrict__ h2g = g_hi + (size_t)ch * HI_STRIDE + c_HOFF[1];
    const float* __restrict__ h1g = g_hi + (size_t)ch * HI_STRIDE;

    const bool int2 = (g2 >= 0) && (g2 + 540 <= Nout2);
    const bool int1 = (g1 >= 0) && (g1 + 1040 <= Nout1);
    stage_vec(bp2s, p2g, g2, 540, Nout2, int2, tid, 256);
    stage_vec(bh2s, h2g, g2, 540, Nout2, int2, tid, 256);
    stage_vec(bh1s, h1g, g1, 1040, Nout1, int1, tid, 256);
    load_filters_smem(filt, ch, 1, sPL1, sPH1, tid);
    if (tid >= 16 && tid < 32) {
        const float2* f2 = reinterpret_cast<const float2*>(filt + ((size_t)ch * 8 + 0) * 64);
        const int j = tid - 16;
        const float2 a = f2[j];
        const float2 bq = f2[16 + j];
        sPL0[j] = pk2(a.y, a.x);
        sPH0[j] = pk2(bq.y, bq.x);
    }
    __syncthreads();

    // level 1: 131 groups of 4 t -> bp1s (masked vs Nout1)
    if (tid < 131) {
        const int rel = 4 * tid;
        ull acc[4];
        inv_group4(bp2s + rel, bh2s + rel, sPL1, sPH1, acc);
        #pragma unroll
        for (int k = 0; k < 4; k++) {
            const int t = T1a + rel + k;
            float oe, oo; unpk2(oe, oo, acc[k]);
            const int idx = 2 * t - g1;
            if ((unsigned)idx       < 1040u) bp1s[idx]     = ((unsigned)(2 * t)     < (unsigned)Nout1) ? oe : 0.0f;
            if ((unsigned)(idx + 1) < 1040u) bp1s[idx + 1] = ((unsigned)(2 * t + 1) < (unsigned)Nout1) ? oo : 0.0f;
        }
    }
    __syncthreads();

    // level 0: exactly 1 group per thread, all outputs valid
    {
        const int rel = 4 * tid;
        ull acc[4];
        inv_group4(bp1s + rel, bh1s + rel, sPL0, sPH0, acc);
        float o[8];
        #pragma unroll
        for (int k = 0; k < 4; k++) unpk2(o[2 * k], o[2 * k + 1], acc[k]);
        float* __restrict__ og = outg + (size_t)ch * TLEN;
        const int n = 2 * (Ta + rel);
        *reinterpret_cast<float4*>(og + n)     = make_float4(o[0], o[1], o[2], o[3]);
        *reinterpret_cast<float4*>(og + n + 4) = make_float4(o[4], o[5], o[6], o[7]);
    }
}

// ---------------------------------------------------------------------------
// mid_kernel: fwd 4-8 + inv 7-2 in smem. inv2 merged: prev3 stays in X,
// hi3 staged into Y/H4 (dead after lvl3), prev2 -> g_bufA.
// ---------------------------------------------------------------------------
#define OX  0
#define OY  16400
#define OH4 24608
#define OH5 32816
#define OH6 36928
#define OH7 38992
#define OH8 40032
#define SM_FLOATS 40576   // +16 pad: inverse windows read a few floats past OH8 region

// forward pair compute (mid kernel): taps (2k,2k+1) from float2 SB2[r+k].
__device__ __forceinline__ ull fwd_pair(const float2* SB2, int r, const ull* W2)
{
    const float2 v0 = SB2[r],     v1 = SB2[r + 1], v2 = SB2[r + 2];
    const float2 v3 = SB2[r + 3], v4 = SB2[r + 4];
    ull a0 = 0ull, a1 = 0ull;
    ffma2(a0, bcast2(v0.x), W2[0]); ffma2(a1, bcast2(v0.y), W2[1]);
    ffma2(a0, bcast2(v1.x), W2[2]); ffma2(a1, bcast2(v1.y), W2[3]);
    ffma2(a0, bcast2(v2.x), W2[4]); ffma2(a1, bcast2(v2.y), W2[5]);
    ffma2(a0, bcast2(v3.x), W2[6]); ffma2(a1, bcast2(v3.y), W2[7]);
    ffma2(a0, bcast2(v4.x), W2[8]); ffma2(a1, bcast2(v4.y), W2[9]);
    add2(a0, a0, a1);
    return a0;
}

__device__ __forceinline__ void fused_fwd_level(
    const float* inb, float* lob, float* hib, int Lout, int tid, const ull* W2)
{
    // data at inb+7; tap base for output j is inb[2 + 2j] -> float2 (inb+2)[j]
    const float2* SB2 = reinterpret_cast<const float2*>(inb + 2);
    float* lod = lob + 7;
    float* hid = hib + 7;
    for (int j = tid; j < Lout; j += FNT) {
        float alo, ahi; unpk2(alo, ahi, fwd_pair(SB2, j, W2));
        lod[j] = alo;
        hid[j] = ahi;
    }
    if (tid < 7)        { lob[tid] = 0.f; hib[tid] = 0.f; }
    else if (tid < 15)  { lod[Lout + tid - 7] = 0.f; hid[Lout + tid - 7] = 0.f; }
}

__device__ __forceinline__ void fused_inv_level(
    const float* prevb, const float* hib, float* outb, int L,
    const ull* sPL, const ull* sPH, int tid)
{
    float* outd = outb + 7;
    const int tmax = L;
    for (int tb = 0; tb < tmax; tb += 4 * FNT) {
        const int t0 = tb + 4 * tid;
        if (t0 < tmax) {
            ull acc[4];
            inv_group4(prevb + t0, hib + t0, sPL, sPH, acc);
            #pragma unroll
            for (int k = 0; k < 4; k++) {
                if (t0 + k < tmax) {
                    float oe, oo;
                    unpk2(oe, oo, acc[k]);
                    outd[2 * (t0 + k)]     = oe;
                    outd[2 * (t0 + k) + 1] = oo;
                }
            }
        }
    }
    __syncthreads();
    const int Nout = 2 * L - 1;
    if (tid < 7)       outb[tid] = 0.f;
    else if (tid < 15) outd[Nout + tid - 7] = 0.f;
}

__global__ void __launch_bounds__(FNT)
mid_kernel(const float* __restrict__ filt)
{
    extern __shared__ __align__(16) float s[];
    __shared__ __align__(16) ull sPL[16], sPH[16];
    const int ch  = blockIdx.x;
    const int tid = threadIdx.x;

    ull W2[10];
    #pragma unroll
    for (int k = 0; k < 10; k++) W2[k] = pk2(c_WLO[k], c_WHI[k]);

    // stage lo_3 (16385 floats) from g_bufB into X
    {
        const float* __restrict__ src = g_bufB + (size_t)ch * 65540;
        float* dst = s + OX + 7;
        for (int q = 4 * tid; q + 3 < 16385; q += 4 * FNT) {
            const float4 v = *reinterpret_cast<const float4*>(src + q);
            dst[q] = v.x; dst[q + 1] = v.y; dst[q + 2] = v.z; dst[q + 3] = v.w;
        }
        if (tid == 0) dst[16384] = src[16384];
        if (tid < 7)       s[OX + tid] = 0.f;
        else if (tid < 15) dst[16385 + tid - 7] = 0.f;
    }
    __syncthreads();

    fused_fwd_level(s + OX, s + OY, s + OH4, 8193, tid, W2);  __syncthreads();
    fused_fwd_level(s + OY, s + OX, s + OH5, 4097, tid, W2);  __syncthreads();
    fused_fwd_level(s + OX, s + OY, s + OH6, 2049, tid, W2);  __syncthreads();
    fused_fwd_level(s + OY, s + OX, s + OH7, 1025, tid, W2);  __syncthreads();
    fused_fwd_level(s + OX, s + OY, s + OH8,  513, tid, W2);  __syncthreads();

    load_filters_smem(filt, ch, 7, sPL, sPH, tid); __syncthreads();
    fused_inv_level(s + OY, s + OH8, s + OX,  513, sPL, sPH, tid); __syncthreads();
    load_filters_smem(filt, ch, 6, sPL, sPH, tid); __syncthreads();
    fused_inv_level(s + OX, s + OH7, s + OY, 1025, sPL, sPH, tid); __syncthreads();
    load_filters_smem(filt, ch, 5, sPL, sPH, tid); __syncthreads();
    fused_inv_level(s + OY, s + OH6, s + OX, 2049, sPL, sPH, tid); __syncthreads();
    load_filters_smem(filt, ch, 4, sPL, sPH, tid); __syncthreads();
    fused_inv_level(s + OX, s + OH5, s + OY, 4097, sPL, sPH, tid); __syncthreads();

    // inverse level 3: Y(prev4)+H4 -> X (prev3 stays in smem)
    load_filters_smem(filt, ch, 3, sPL, sPH, tid); __syncthreads();
    fused_inv_level(s + OY, s + OH4, s + OX, 8193, sPL, sPH, tid); __syncthreads();

    // stage hi3 (16385) from global into Y∪H4 region (dead; 16416 floats avail)
    {
        const float* __restrict__ src = g_hi + (size_t)ch * HI_STRIDE + c_HOFF[2];
        float* dst = s + OY + 7;
        for (int q = 4 * tid; q + 3 < 16385; q += 4 * FNT) {
            const float4 v = *reinterpret_cast<const float4*>(src + q);
            dst[q] = v.x; dst[q + 1] = v.y; dst[q + 2] = v.z; dst[q + 3] = v.w;
        }
        if (tid == 0) dst[16384] = src[16384];
        if (tid < 7)       s[OY + tid] = 0.f;
        else if (tid < 15) dst[16385 + tid - 7] = 0.f;
    }
    load_filters_smem(filt, ch, 2, sPL, sPH, tid);
    __syncthreads();

    // inverse level 2: X(prev3)+Y(hi3) -> g_bufA (prev2, 32769)
    {
        const float* prevb = s + OX;
        const float* hib   = s + OY;
        float* __restrict__ out = g_bufA + (size_t)ch * 32772;
        const int tmax = 16385, Nout = 32769;
        for (int tb = 0; tb < tmax; tb += 4 * FNT) {
            const int t0 = tb + 4 * tid;
            if (t0 >= tmax) break;
            ull acc[4];
            inv_group4(prevb + t0, hib + t0, sPL, sPH, acc);
            float o[8];
            #pragma unroll
            for (int k = 0; k < 4; k++) unpk2(o[2 * k], o[2 * k + 1], acc[k]);
            const int n0 = 2 * t0;
            if (n0 + 7 < Nout && t0 + 3 < tmax) {
                *reinterpret_cast<float4*>(out + n0)     = make_float4(o[0], o[1], o[2], o[3]);
                *reinterpret_cast<float4*>(out + n0 + 4) = make_float4(o[4], o[5], o[6], o[7]);
            } else {
                #pragma unroll
                for (int k = 0; k < 4; k++) {
                    if (t0 + k < tmax) {
                        const int n = n0 + 2 * k;
                        if (n < Nout)     out[n]     = o[2 * k];
                        if (n + 1 < Nout) out[n + 1] = o[2 * k + 1];
                    }
                }
            }
        }
    }
}

// ---------------------------------------------------------------------------
extern "C" void kernel_launch(void* const* d_in, const int* in_sizes, int n_in,
                              void* d_out, int out_size)
{
    const float* x    = (const float*)d_in[0];
    const float* filt = (const float*)d_in[1];
    if (n_in >= 2 && in_sizes[0] < in_sizes[1]) {
        x    = (const float*)d_in[1];
        filt = (const float*)d_in[0];
    }
    float* out = (float*)d_out;

    cudaFuncSetAttribute(fwd123, cudaFuncAttributeMaxDynamicSharedMemorySize, FW_SMEM);
    cudaFuncSetAttribute(mid_kernel, cudaFuncAttributeMaxDynamicSharedMemorySize,
                         SM_FLOATS * (int)sizeof(float));

    // fwd levels 1-3: 33 blocks of 512 lo3 outputs
    {
        dim3 grid(33, NCH);
        fwd123<<<grid, 256, FW_SMEM>>>(x);
    }
    // fwd 4-8 + inv 7-2 (inv2 merged)
    mid_kernel<<<NCH, FNT, SM_FLOATS * sizeof(float)>>>(filt);
    // inv levels 1+0: 64 blocks of 1024 t
    {
        dim3 grid(64, NCH);
        inv10<<<grid, 256>>>(filt, out);
    }
}

// round 17
// speedup vs baseline: 1.0320x; 1.0320x over previous
#include <cuda_runtime.h>

// ---------------------------------------------------------------------------
// WaveletConv in 3 launches (R15 config; fwd123 capped at 42 regs for 6 CTA/SM):
//   fwd123 : fwd levels 1-3 fused (halo recompute), x -> lo3 + hi1..hi3
//   mid    : fwd 4-8 + inv 7-2 fused per-channel in smem (lo3 -> prev2);
//            inv2 merged in: prev3 stays in smem, hi3 staged, prev2 -> global
//   inv10  : inv levels 1-0 fused, prev2 + hi2 + hi1 -> out (frozen optimum)
// Packed f32x2 FMA; conflict-free LDS.128 windows; CTA-uniform packed
// filters in shared memory, fetched as ulonglong2 pairs (broadcast LDS.128).
// ---------------------------------------------------------------------------

#define NCH      128
#define TLEN     131072
#define FNT      512    // mid kernel threads

// hi offsets padded to multiples of 4 floats (16B)
__device__ __constant__ int c_HOFF[8] = {0, 65540, 98312, 114700, 122896, 126996, 129048, 130076};
#define HI_STRIDE 130592

__device__ __constant__ float c_WLO[10] = {0.003335725285001549f, -0.012580751999015526f,
    -0.006241490213011705f, 0.07757149384006515f, -0.03224486958502952f,
    -0.24229488706619015f, 0.13842814590110342f, 0.7243085284385744f,
    0.6038292697974729f, 0.160102397974125f};
__device__ __constant__ float c_WHI[10] = {-0.160102397974125f, 0.6038292697974729f,
    -0.7243085284385744f, 0.13842814590110342f, 0.24229488706619015f,
    -0.03224486958502952f, -0.07757149384006515f, -0.006241490213011705f,
    0.012580751999015526f, 0.003335725285001549f};

// Static scratch (allocation-free rule)
__device__ __align__(16) float g_hi[NCH * HI_STRIDE];    // hi1..hi8
__device__ __align__(16) float g_bufA[NCH * 32772];      // prev2
__device__ __align__(16) float g_bufB[NCH * 65540];      // lo3

// ---- packed f32x2 helpers --------------------------------------------------
typedef unsigned long long ull;

__device__ __forceinline__ ull pk2(float lo, float hi) {
    ull r; asm("mov.b64 %0, {%1, %2};" : "=l"(r) : "f"(lo), "f"(hi)); return r;
}
__device__ __forceinline__ ull bcast2(float v) {
    ull r; asm("mov.b64 %0, {%1, %1};" : "=l"(r) : "f"(v)); return r;
}
__device__ __forceinline__ void ffma2(ull& d, ull a, ull b) {
    asm("fma.rn.f32x2 %0, %1, %2, %3;" : "=l"(d) : "l"(a), "l"(b), "l"(d));
}
__device__ __forceinline__ void add2(ull& d, ull a, ull b) {
    asm("add.rn.f32x2 %0, %1, %2;" : "=l"(d) : "l"(a), "l"(b));
}
__device__ __forceinline__ void unpk2(float& lo, float& hi, ull r) {
    asm("mov.b64 {%0, %1}, %2;" : "=f"(lo), "=f"(hi) : "l"(r));
}

// forward pair compute: taps (2k,2k+1) from float2 SB2[r+k], dual chains.
__device__ __forceinline__ ull fwd_pair(const float2* SB2, int r, const ull* W2)
{
    const float2 v0 = SB2[r],     v1 = SB2[r + 1], v2 = SB2[r + 2];
    const float2 v3 = SB2[r + 3], v4 = SB2[r + 4];
    ull a0 = 0ull, a1 = 0ull;
    ffma2(a0, bcast2(v0.x), W2[0]); ffma2(a1, bcast2(v0.y), W2[1]);
    ffma2(a0, bcast2(v1.x), W2[2]); ffma2(a1, bcast2(v1.y), W2[3]);
    ffma2(a0, bcast2(v2.x), W2[4]); ffma2(a1, bcast2(v2.y), W2[5]);
    ffma2(a0, bcast2(v3.x), W2[6]); ffma2(a1, bcast2(v3.y), W2[7]);
    ffma2(a0, bcast2(v4.x), W2[8]); ffma2(a1, bcast2(v4.y), W2[9]);
    add2(a0, a0, a1);
    return a0;
}

// load 20 floats from 16B-aligned smem pointer via 5 conflict-free LDS.128
__device__ __forceinline__ void load20(float* w, const float* p)
{
    const float4* q = reinterpret_cast<const float4*>(p);
    #pragma unroll
    for (int v = 0; v < 5; v++) {
        const float4 t = q[v];
        w[4 * v] = t.x; w[4 * v + 1] = t.y; w[4 * v + 2] = t.z; w[4 * v + 3] = t.w;
    }
}

// 4-t group: acc[k] += P[j] * w[j+k]. P is 16B-aligned CTA-uniform shared;
// fetch filter pairs as one broadcast LDS.128 (halves filter LDS count).
// Per-accumulator add order stays j-ascending -> bit-identical numerics.
__device__ __forceinline__ void inv_acc4(const float* w, const ull* P, ull* acc)
{
    #pragma unroll
    for (int j = 0; j < 16; j += 2) {
        const ulonglong2 pj2 = *reinterpret_cast<const ulonglong2*>(P + j);
        ffma2(acc[0], bcast2(w[j]),     pj2.x);
        ffma2(acc[1], bcast2(w[j + 1]), pj2.x);
        ffma2(acc[2], bcast2(w[j + 2]), pj2.x);
        ffma2(acc[3], bcast2(w[j + 3]), pj2.x);
        ffma2(acc[0], bcast2(w[j + 1]), pj2.y);
        ffma2(acc[1], bcast2(w[j + 2]), pj2.y);
        ffma2(acc[2], bcast2(w[j + 3]), pj2.y);
        ffma2(acc[3], bcast2(w[j + 4]), pj2.y);
    }
}

// full inverse group: 4 consecutive t from smem windows sp/sh (16B-aligned).
__device__ __forceinline__ void inv_group4(const float* sp, const float* sh,
                                           const ull* PL, const ull* PH, ull* acc)
{
    acc[0] = acc[1] = acc[2] = acc[3] = 0ull;
    float w[20];
    load20(w, sp); inv_acc4(w, PL, acc);
    load20(w, sh); inv_acc4(w, PH, acc);
}

// load packed per-(channel,level) filters into CTA shared arrays (tid<16).
// Caller must __syncthreads() before using them.
__device__ __forceinline__ void load_filters_smem(
    const float* __restrict__ filt, int ch, int i, ull* sPL, ull* sPH, int tid)
{
    if (tid < 16) {
        const float2* f2 = reinterpret_cast<const float2*>(filt + ((size_t)ch * 8 + (size_t)i) * 64);
        const float2 a = f2[tid];
        const float2 b = f2[16 + tid];
        sPL[tid] = pk2(a.y, a.x);
        sPH[tid] = pk2(b.y, b.x);
    }
}

// stage `cnt` floats from src[base..base+cnt) into smem buf (buf[q]=src[base+q]).
__device__ __forceinline__ void stage_vec(float* buf, const float* __restrict__ src,
                                          int base, int cnt, int len, bool interior, int tid, int nthr)
{
    if (interior) {
        if (tid < 3) buf[tid] = src[base + tid];
        const int nv = (cnt - 3) >> 2;              // float4 count
        const int rem = cnt - 3 - 4 * nv;           // 0..3 tail scalars
        if (tid >= 3 && tid < 3 + rem) buf[cnt - 1 - (tid - 3)] = src[base + cnt - 1 - (tid - 3)];
        const float4* s4 = reinterpret_cast<const float4*>(src + base + 3);
        for (int v = tid; v < nv; v += nthr) {
            const float4 w = s4[v];
            const int q = 3 + 4 * v;
            buf[q] = w.x; buf[q + 1] = w.y; buf[q + 2] = w.z; buf[q + 3] = w.w;
        }
    } else {
        for (int q = tid; q < cnt; q += nthr) {
            const int g = base + q;
            buf[q] = ((unsigned)g < (unsigned)len) ? src[g] : 0.0f;
        }
    }
}

// ---------------------------------------------------------------------------
// fwd123: levels 1-3. CTA owns lo3[c3, c3+512); recomputes lo1/lo2 in smem.
// launch_bounds(256,6): cap regs at 42 -> 6 CTAs/SM (was 5 at 48 regs).
// ---------------------------------------------------------------------------
#define FW_D3  512
#define FW_SX  4160   // >= szx = 4152
#define FW_SL1 2080   // >= sz1 = 2072
#define FW_SMEM ((FW_SX + FW_SL1) * 4)

__global__ void __launch_bounds__(256, 6)
fwd123(const float* __restrict__ x)
{
    extern __shared__ __align__(16) float s[];
    float* SX  = s;             // x stage; aliased by lo2 later
    float* SL1 = s + FW_SX;
    float* SL2 = s;

    const int ch = blockIdx.y, b = blockIdx.x, tid = threadIdx.x;
    const int L1 = 65537, L2 = 32769, L3 = 16385;

    const int c3 = b * FW_D3;
    const int d3  = min(c3 + FW_D3, L3);
    const int a2  = 2 * c3 - 5, sz2 = 2 * (d3 - c3) + 8;
    const int a1  = 2 * a2 - 5, sz1 = 2 * sz2 + 8;
    const int ax  = 2 * a1 - 5, szx = 2 * sz1 + 8;

    const float* __restrict__ xr = x + (size_t)ch * TLEN;
    const bool xint = (ax >= 0) && (ax + szx <= TLEN);
    stage_vec(SX, xr, ax, szx, TLEN, xint, tid, 256);
    __syncthreads();

    ull W2[10];
    #pragma unroll
    for (int k = 0; k < 10; k++) W2[k] = pk2(c_WLO[k], c_WHI[k]);

    // ---- level 1: SX -> SL1 (lo1), hi1 -> global owned window ----
    {
        float* __restrict__ hi1 = g_hi + (size_t)ch * HI_STRIDE;
        const int hlo = 4 * c3;
        const int hhi = min(4 * c3 + 4 * FW_D3, L1);
        const float2* SB2 = reinterpret_cast<const float2*>(SX);
        for (int q = tid; q < sz1; q += 256) {
            const int n = a1 + q;
            float alo, ahi; unpk2(alo, ahi, fwd_pair(SB2, q, W2));
            const bool valid = (unsigned)n < (unsigned)L1;
            SL1[q] = valid ? alo : 0.0f;
            if (valid && n >= hlo && n < hhi) hi1[n] = ahi;
        }
    }
    __syncthreads();

    // ---- level 2: SL1 -> SL2 (aliases SX), hi2 -> global owned window ----
    {
        float* __restrict__ hi2 = g_hi + (size_t)ch * HI_STRIDE + c_HOFF[1];
        const int hlo = 2 * c3;
        const int hhi = min(2 * c3 + 2 * FW_D3, L2);
        const float2* SB2 = reinterpret_cast<const float2*>(SL1);
        for (int q = tid; q < sz2; q += 256) {
            const int n = a2 + q;
            float alo, ahi; unpk2(alo, ahi, fwd_pair(SB2, q, W2));
            const bool valid = (unsigned)n < (unsigned)L2;
            SL2[q] = valid ? alo : 0.0f;
            if (valid && n >= hlo && n < hhi) hi2[n] = ahi;
        }
    }
    __syncthreads();

    // ---- level 3: SL2 -> lo3 + hi3 global ----
    {
        float* __restrict__ lo3 = g_bufB + (size_t)ch * 65540;
        float* __restrict__ hi3 = g_hi + (size_t)ch * HI_STRIDE + c_HOFF[2];
        const float2* SB2 = reinterpret_cast<const float2*>(SL2);
        for (int j = c3 + tid; j < d3; j += 256) {
            float alo, ahi; unpk2(alo, ahi, fwd_pair(SB2, j - c3, W2));
            lo3[j] = alo;
            hi3[j] = ahi;
        }
    }
}

// ---------------------------------------------------------------------------
// inv10: levels 1+0 fused (frozen optimum). CTA owns 1024 level-0 t values.
// ---------------------------------------------------------------------------
__global__ void __launch_bounds__(256)
inv10(const float* __restrict__ filt, float* __restrict__ outg)
{
    __shared__ __align__(16) float bp2s[544], bh2s[544];
    __shared__ __align__(16) float bh1s[1040];
    __shared__ __align__(16) float bp1s[1048];
    __shared__ __align__(16) ull sPL1[16], sPH1[16], sPL0[16], sPH0[16];

    const int ch = blockIdx.y, b = blockIdx.x, tid = threadIdx.x;
    const int Nout1 = 65537, Nout2 = 32769;

    const int Ta  = 1024 * b;       // level-0 t range [Ta, Ta+1024)
    const int g1  = Ta - 7;         // prev1/hi1 buffer origin
    const int T1a = 512 * b - 4;    // level-1 first t (mult of 4)
    const int g2  = T1a - 7;        // prev2/hi2 buffer origin

    const float* __restrict__ p2g = g_bufA + (size_t)ch * 32772;
    const float* __restrict__ h2g = g_hi + (size_t)ch * HI_STRIDE + c_HOFF[1];
    const float* __restrict__ h1g = g_hi + (size_t)ch * HI_STRIDE;

    const bool int2 = (g2 >= 0) && (g2 + 540 <= Nout2);
    const bool int1 = (g1 >= 0) && (g1 + 1040 <= Nout1);
    stage_vec(bp2s, p2g, g2, 540, Nout2, int2, tid, 256);
    stage_vec(bh2s, h2g, g2, 540, Nout2, int2, tid, 256);
    stage_vec(bh1s, h1g, g1, 1040, Nout1, int1, tid, 256);
    load_filters_smem(filt, ch, 1, sPL1, sPH1, tid);
    if (tid >= 16 && tid < 32) {
        const float2* f2 = reinterpret_cast<const float2*>(filt + ((size_t)ch * 8 + 0) * 64);
        const int j = tid - 16;
        const float2 a = f2[j];
        const float2 bq = f2[16 + j];
        sPL0[j] = pk2(a.y, a.x);
        sPH0[j] = pk2(bq.y, bq.x);
    }
    __syncthreads();

    // level 1: 131 groups of 4 t -> bp1s (masked vs Nout1)
    if (tid < 131) {
        const int rel = 4 * tid;
        ull acc[4];
        inv_group4(bp2s + rel, bh2s + rel, sPL1, sPH1, acc);
        #pragma unroll
        for (int k = 0; k < 4; k++) {
            const int t = T1a + rel + k;
            float oe, oo; unpk2(oe, oo, acc[k]);
            const int idx = 2 * t - g1;
            if ((unsigned)idx       < 1040u) bp1s[idx]     = ((unsigned)(2 * t)     < (unsigned)Nout1) ? oe : 0.0f;
            if ((unsigned)(idx + 1) < 1040u) bp1s[idx + 1] = ((unsigned)(2 * t + 1) < (unsigned)Nout1) ? oo : 0.0f;
        }
    }
    __syncthreads();

    // level 0: exactly 1 group per thread, all outputs valid
    {
        const int rel = 4 * tid;
        ull acc[4];
        inv_group4(bp1s + rel, bh1s + rel, sPL0, sPH0, acc);
        float o[8];
        #pragma unroll
        for (int k = 0; k < 4; k++) unpk2(o[2 * k], o[2 * k + 1], acc[k]);
        float* __restrict__ og = outg + (size_t)ch * TLEN;
        const int n = 2 * (Ta + rel);
        *reinterpret_cast<float4*>(og + n)     = make_float4(o[0], o[1], o[2], o[3]);
        *reinterpret_cast<float4*>(og + n + 4) = make_float4(o[4], o[5], o[6], o[7]);
    }
}

// ---------------------------------------------------------------------------
// mid_kernel: fwd 4-8 + inv 7-2 in smem. inv2 merged: prev3 stays in X,
// hi3 staged into Y/H4 (dead after lvl3), prev2 -> g_bufA.
// ---------------------------------------------------------------------------
#define OX  0
#define OY  16400
#define OH4 24608
#define OH5 32816
#define OH6 36928
#define OH7 38992
#define OH8 40032
#define SM_FLOATS 40576   // +16 pad: inverse windows read a few floats past OH8 region

__device__ __forceinline__ void fused_fwd_level(
    const float* inb, float* lob, float* hib, int Lout, int tid, const ull* W2)
{
    // data at inb+7; tap base for output j is inb[2 + 2j] -> float2 (inb+2)[j]
    const float2* SB2 = reinterpret_cast<const float2*>(inb + 2);
    float* lod = lob + 7;
    float* hid = hib + 7;
    for (int j = tid; j < Lout; j += FNT) {
        float alo, ahi; unpk2(alo, ahi, fwd_pair(SB2, j, W2));
        lod[j] = alo;
        hid[j] = ahi;
    }
    if (tid < 7)        { lob[tid] = 0.f; hib[tid] = 0.f; }
    else if (tid < 15)  { lod[Lout + tid - 7] = 0.f; hid[Lout + tid - 7] = 0.f; }
}

__device__ __forceinline__ void fused_inv_level(
    const float* prevb, const float* hib, float* outb, int L,
    const ull* sPL, const ull* sPH, int tid)
{
    float* outd = outb + 7;
    const int tmax = L;
    for (int tb = 0; tb < tmax; tb += 4 * FNT) {
        const int t0 = tb + 4 * tid;
        if (t0 < tmax) {
            ull acc[4];
            inv_group4(prevb + t0, hib + t0, sPL, sPH, acc);
            #pragma unroll
            for (int k = 0; k < 4; k++) {
                if (t0 + k < tmax) {
                    float oe, oo;
                    unpk2(oe, oo, acc[k]);
                    outd[2 * (t0 + k)]     = oe;
                    outd[2 * (t0 + k) + 1] = oo;
                }
            }
        }
    }
    __syncthreads();
    const int Nout = 2 * L - 1;
    if (tid < 7)       outb[tid] = 0.f;
    else if (tid < 15) outd[Nout + tid - 7] = 0.f;
}

__global__ void __launch_bounds__(FNT)
mid_kernel(const float* __restrict__ filt)
{
    extern __shared__ __align__(16) float s[];
    __shared__ __align__(16) ull sPL[16], sPH[16];
    const int ch  = blockIdx.x;
    const int tid = threadIdx.x;

    ull W2[10];
    #pragma unroll
    for (int k = 0; k < 10; k++) W2[k] = pk2(c_WLO[k], c_WHI[k]);

    // stage lo_3 (16385 floats) from g_bufB into X
    {
        const float* __restrict__ src = g_bufB + (size_t)ch * 65540;
        float* dst = s + OX + 7;
        for (int q = 4 * tid; q + 3 < 16385; q += 4 * FNT) {
            const float4 v = *reinterpret_cast<const float4*>(src + q);
            dst[q] = v.x; dst[q + 1] = v.y; dst[q + 2] = v.z; dst[q + 3] = v.w;
        }
        if (tid == 0) dst[16384] = src[16384];
        if (tid < 7)       s[OX + tid] = 0.f;
        else if (tid < 15) dst[16385 + tid - 7] = 0.f;
    }
    __syncthreads();

    fused_fwd_level(s + OX, s + OY, s + OH4, 8193, tid, W2);  __syncthreads();
    fused_fwd_level(s + OY, s + OX, s + OH5, 4097, tid, W2);  __syncthreads();
    fused_fwd_level(s + OX, s + OY, s + OH6, 2049, tid, W2);  __syncthreads();
    fused_fwd_level(s + OY, s + OX, s + OH7, 1025, tid, W2);  __syncthreads();
    fused_fwd_level(s + OX, s + OY, s + OH8,  513, tid, W2);  __syncthreads();

    load_filters_smem(filt, ch, 7, sPL, sPH, tid); __syncthreads();
    fused_inv_level(s + OY, s + OH8, s + OX,  513, sPL, sPH, tid); __syncthreads();
    load_filters_smem(filt, ch, 6, sPL, sPH, tid); __syncthreads();
    fused_inv_level(s + OX, s + OH7, s + OY, 1025, sPL, sPH, tid); __syncthreads();
    load_filters_smem(filt, ch, 5, sPL, sPH, tid); __syncthreads();
    fused_inv_level(s + OY, s + OH6, s + OX, 2049, sPL, sPH, tid); __syncthreads();
    load_filters_smem(filt, ch, 4, sPL, sPH, tid); __syncthreads();
    fused_inv_level(s + OX, s + OH5, s + OY, 4097, sPL, sPH, tid); __syncthreads();

    // inverse level 3: Y(prev4)+H4 -> X (prev3 stays in smem)
    load_filters_smem(filt, ch, 3, sPL, sPH, tid); __syncthreads();
    fused_inv_level(s + OY, s + OH4, s + OX, 8193, sPL, sPH, tid); __syncthreads();

    // stage hi3 (16385) from global into Y∪H4 region (dead; 16416 floats avail)
    {
        const float* __restrict__ src = g_hi + (size_t)ch * HI_STRIDE + c_HOFF[2];
        float* dst = s + OY + 7;
        for (int q = 4 * tid; q + 3 < 16385; q += 4 * FNT) {
            const float4 v = *reinterpret_cast<const float4*>(src + q);
            dst[q] = v.x; dst[q + 1] = v.y; dst[q + 2] = v.z; dst[q + 3] = v.w;
        }
        if (tid == 0) dst[16384] = src[16384];
        if (tid < 7)       s[OY + tid] = 0.f;
        else if (tid < 15) dst[16385 + tid - 7] = 0.f;
    }
    load_filters_smem(filt, ch, 2, sPL, sPH, tid);
    __syncthreads();

    // inverse level 2: X(prev3)+Y(hi3) -> g_bufA (prev2, 32769)
    {
        const float* prevb = s + OX;
        const float* hib   = s + OY;
        float* __restrict__ out = g_bufA + (size_t)ch * 32772;
        const int tmax = 16385, Nout = 32769;
        for (int tb = 0; tb < tmax; tb += 4 * FNT) {
            const int t0 = tb + 4 * tid;
            if (t0 >= tmax) break;
            ull acc[4];
            inv_group4(prevb + t0, hib + t0, sPL, sPH, acc);
            float o[8];
            #pragma unroll
            for (int k = 0; k < 4; k++) unpk2(o[2 * k], o[2 * k + 1], acc[k]);
            const int n0 = 2 * t0;
            if (n0 + 7 < Nout && t0 + 3 < tmax) {
                *reinterpret_cast<float4*>(out + n0)     = make_float4(o[0], o[1], o[2], o[3]);
                *reinterpret_cast<float4*>(out + n0 + 4) = make_float4(o[4], o[5], o[6], o[7]);
            } else {
                #pragma unroll
                for (int k = 0; k < 4; k++) {
                    if (t0 + k < tmax) {
                        const int n = n0 + 2 * k;
                        if (n < Nout)     out[n]     = o[2 * k];
                        if (n + 1 < Nout) out[n + 1] = o[2 * k + 1];
                    }
                }
            }
        }
    }
}

// ---------------------------------------------------------------------------
extern "C" void kernel_launch(void* const* d_in, const int* in_sizes, int n_in,
                              void* d_out, int out_size)
{
    const float* x    = (const float*)d_in[0];
    const float* filt = (const float*)d_in[1];
    if (n_in >= 2 && in_sizes[0] < in_sizes[1]) {
        x    = (const float*)d_in[1];
        filt = (const float*)d_in[0];
    }
    float* out = (float*)d_out;

    cudaFuncSetAttribute(fwd123, cudaFuncAttributeMaxDynamicSharedMemorySize, FW_SMEM);
    cudaFuncSetAttribute(mid_kernel, cudaFuncAttributeMaxDynamicSharedMemorySize,
                         SM_FLOATS * (int)sizeof(float));

    // fwd levels 1-3: 33 blocks of 512 lo3 outputs
    {
        dim3 grid(33, NCH);
        fwd123<<<grid, 256, FW_SMEM>>>(x);
    }
    // fwd 4-8 + inv 7-2 (inv2 merged)
    mid_kernel<<<NCH, FNT, SM_FLOATS * sizeof(float)>>>(filt);
    // inv levels 1+0: 64 blocks of 1024 t
    {
        dim3 grid(64, NCH);
        inv10<<<grid, 256>>>(filt, out);
    }
}